// round 12
// baseline (speedup 1.0000x reference)
#include <cuda_runtime.h>
#include <cuda_bf16.h>
#include <math.h>
#include <cstdint>

// ---------------------------------------------------------------------------
// Problem constants
#define BATCH   256
#define IN_CH   1152
#define OUT_CH  10
#define OUT_U   16
#define NIK     9216             // IN_CH*8, contraction dim for s-GEMM
#define OUD     160              // OUT_CH*OUT_U
#define KSPLIT  72
#define SOUT    40960            // BATCH*OUD
#define MO      (NIK*OUD)        // 1474560

// ---------------------------------------------------------------------------
// Device scratch (allocation-free)
__device__ __align__(16) __nv_bfloat16 g_xh[BATCH * NIK], g_xl[BATCH * NIK];   // x split  [b][ik]
__device__ __align__(16) __nv_bfloat16 g_xTh[NIK * BATCH], g_xTl[NIK * BATCH]; // x^T split[ik][b]
__device__ __align__(16) __nv_bfloat16 g_Wsh[MO], g_Wsl[MO];                   // W split [ou][ik]
__device__ __align__(16) __nv_bfloat16 g_vTh[OUD * BATCH], g_vTl[OUD * BATCH]; // v^T split [ou][b]
__device__ __align__(16) float g_spart[KSPLIT * SOUT];   // s split-K partials
__device__ __align__(16) float g_spart2[8 * SOUT];       // stage-1 reduced
__device__ __align__(16) float g_mpart[2 * MO];          // M = x^T v, 2 halves
__device__ float g_blog[IN_CH * OUT_CH];
__device__ float g_c[IN_CH * OUT_CH];

// ---------------------------------------------------------------------------
#define MMA_BF16(c, A0, A1, A2, A3, B0, B1)                                   \
    asm volatile("mma.sync.aligned.m16n8k16.row.col.f32.bf16.bf16.f32 "       \
                 "{%0,%1,%2,%3}, {%4,%5,%6,%7}, {%8,%9}, {%0,%1,%2,%3};"      \
                 : "+f"((c)[0]), "+f"((c)[1]), "+f"((c)[2]), "+f"((c)[3])     \
                 : "r"(A0), "r"(A1), "r"(A2), "r"(A3), "r"(B0), "r"(B1))

__device__ __forceinline__ uint32_t smem_u32(const void* p) {
    uint32_t a;
    asm("{ .reg .u64 t; cvta.to.shared.u64 t, %1; cvt.u32.u64 %0, t; }" : "=r"(a) : "l"(p));
    return a;
}
__device__ __forceinline__ void cpa16(uint32_t dst, const void* src) {
    asm volatile("cp.async.cg.shared.global [%0], [%1], 16;" :: "r"(dst), "l"(src));
}
#define CP_COMMIT() asm volatile("cp.async.commit_group;" ::: "memory")
#define CP_WAIT0()  asm volatile("cp.async.wait_group 0;" ::: "memory")

// smem geometry: K-chunk = 32 bf16 = 16 u32 words/row, stride 20 words
// (qrow*20+qcol mod 32 covers {0,20,8,28,16,4,24,12}+0..3 = all 32 banks).
#define SROW  20
#define W_AH  0
#define W_AL  1280                     // 64*20
#define W_BH  2560
#define W_BL  5760                     // +160*20
#define W_BUF 8960                     // words per buffer
#define SM_TOTAL (2 * W_BUF * 4)       // 71680 bytes

// ---------------------------------------------------------------------------
__global__ void k_init() {
    int t = blockIdx.x * 256 + threadIdx.x;
    if (t < IN_CH * OUT_CH) { g_blog[t] = 0.0f; g_c[t] = 0.1f; }
}

// One-time W -> bf16 hi/lo split in [ou][ik] layout (output-coalesced).
__global__ void k_splitW(const float* __restrict__ W) {
    int idx = blockIdx.x * 256 + threadIdx.x;     // < MO, = ou*NIK+ik
    int ou = idx / NIK, ik = idx - ou * NIK;
    float f = __ldg(&W[(size_t)(ik >> 3) * 1280 + ou * 8 + (ik & 7)]);
    __nv_bfloat16 h = __float2bfloat16(f);
    g_Wsh[idx] = h;
    g_Wsl[idx] = __float2bfloat16(f - __bfloat162float(h));
}

// x -> bf16 hi/lo split in BOTH [b][ik] and [ik][b] layouts (single x read).
__global__ void k_split_x(const float* __restrict__ x) {
    __shared__ float s[32][33];
    int ik0 = blockIdx.x * 32, b0 = blockIdx.y * 32;
    int t = threadIdx.x, tr = t >> 5, tc = t & 31;
#pragma unroll
    for (int j = 0; j < 4; j++)
        s[tr + 8 * j][tc] = x[(size_t)(b0 + tr + 8 * j) * NIK + ik0 + tc];
    __syncthreads();
#pragma unroll
    for (int j = 0; j < 4; j++) {
        int r = tr + 8 * j;
        float f = s[r][tc];
        __nv_bfloat16 h = __float2bfloat16(f);
        size_t o = (size_t)(b0 + r) * NIK + ik0 + tc;
        g_xh[o] = h;
        g_xl[o] = __float2bfloat16(f - __bfloat162float(h));
        float ft = s[tc][r];
        __nv_bfloat16 h2 = __float2bfloat16(ft);
        size_t o2 = (size_t)(ik0 + r) * BATCH + b0 + tc;
        g_xTh[o2] = h2;
        g_xTl[o2] = __float2bfloat16(ft - __bfloat162float(h2));
    }
}

// ---------------------------------------------------------------------------
// Pipelined warp-MMA GEMM: D[64 x 160] += A[64 x 128k] · B[160 x 128k]^T.
// K staged in 4 chunks of 32 with cp.async double buffering.
// mode 0 (s-GEMM): A=x[b][ik], B=(c∘W)[ou][ik] built on the fly. grid (72,4).
// mode 1 (M-GEMM): A=xT[ik][b], B=vT[ou][b].                     grid (144,2).
__global__ __launch_bounds__(256, 2) void k_mma(int mode) {
    extern __shared__ uint32_t sm4[];
    uint32_t smb = smem_u32(sm4);
    int t = threadIdx.x;

    const __nv_bfloat16 *Ah_g, *Al_g, *Bh_g, *Bl_g;
    int astr, bstr, arow0, k0;
    float* outp;
    if (mode == 0) {
        Ah_g = g_xh;  Al_g = g_xl;  astr = NIK;   arow0 = blockIdx.y * 64;
        Bh_g = g_Wsh; Bl_g = g_Wsl; bstr = NIK;   k0 = blockIdx.x * 128;
        outp = g_spart + (size_t)blockIdx.x * SOUT;
    } else {
        Ah_g = g_xTh; Al_g = g_xTl; astr = BATCH; arow0 = blockIdx.x * 64;
        Bh_g = g_vTh; Bl_g = g_vTl; bstr = BATCH; k0 = blockIdx.y * 128;
        outp = g_mpart + (size_t)blockIdx.y * MO;
    }

    int ar = t >> 2, aseg = t & 3;                 // A staging: 1 uint4/thread

    // --- stage A chunk via cp.async into buffer bw ---
    auto stageA = [&](int bw, int kc) {
        size_t ga = (size_t)(arow0 + ar) * astr + kc + aseg * 8;
        uint32_t d = smb + (bw + ar * SROW + aseg * 4) * 4;
        cpa16(d, Ah_g + ga);
        cpa16(d + W_AL * 4, Al_g + ga);
    };
    // --- stage B chunk via cp.async (mode 1) ---
    auto stageB1 = [&](int bw, int kc) {
#pragma unroll
        for (int it = 0; it < 3; it++) {
            int idx = t + 256 * it;
            if (idx < 640) {
                int r = idx >> 2, seg = idx & 3;
                size_t g = (size_t)r * bstr + kc + seg * 8;
                uint32_t d = smb + (bw + W_BH + r * SROW + seg * 4) * 4;
                cpa16(d, Bh_g + g);
                cpa16(d + (W_BL - W_BH) * 4, Bl_g + g);
            }
        }
    };
    // --- mode 0 B: prefetch W(+c) into regs, then convert + STS ---
    uint4 ph[3], pl[3];
    float pcv[3];
    auto prefB0 = [&](int kc) {
#pragma unroll
        for (int it = 0; it < 3; it++) {
            int idx = t + 256 * it;
            if (idx < 640) {
                int r = idx >> 2, seg = idx & 3;
                size_t g = (size_t)r * NIK + kc + seg * 8;
                ph[it] = *reinterpret_cast<const uint4*>(Bh_g + g);
                pl[it] = *reinterpret_cast<const uint4*>(Bl_g + g);
                pcv[it] = __ldg(&g_c[((kc >> 3) + seg) * 10 + (r >> 4)]);
            }
        }
    };
    auto stsB0 = [&](int bw) {
#pragma unroll
        for (int it = 0; it < 3; it++) {
            int idx = t + 256 * it;
            if (idx < 640) {
                int r = idx >> 2, seg = idx & 3;
                float c = pcv[it];
                uint32_t hw[4] = {ph[it].x, ph[it].y, ph[it].z, ph[it].w};
                uint32_t lw[4] = {pl[it].x, pl[it].y, pl[it].z, pl[it].w};
                uint32_t oh[4], ol[4];
#pragma unroll
                for (int q = 0; q < 4; q++) {
                    float2 fh = __bfloat1622float2(*reinterpret_cast<__nv_bfloat162*>(&hw[q]));
                    float2 fl = __bfloat1622float2(*reinterpret_cast<__nv_bfloat162*>(&lw[q]));
                    float f0 = c * (fh.x + fl.x), f1 = c * (fh.y + fl.y);
                    __nv_bfloat162 nh = __floats2bfloat162_rn(f0, f1);
                    float2 nhf = __bfloat1622float2(nh);
                    __nv_bfloat162 nl = __floats2bfloat162_rn(f0 - nhf.x, f1 - nhf.y);
                    oh[q] = *reinterpret_cast<uint32_t*>(&nh);
                    ol[q] = *reinterpret_cast<uint32_t*>(&nl);
                }
                int w = bw + W_BH + r * SROW + seg * 4;
                *reinterpret_cast<uint4*>(sm4 + w) = make_uint4(oh[0], oh[1], oh[2], oh[3]);
                *reinterpret_cast<uint4*>(sm4 + w + (W_BL - W_BH)) =
                    make_uint4(ol[0], ol[1], ol[2], ol[3]);
            }
        }
    };

    int wid = t >> 5, lane = t & 31;
    int wm = wid & 1, wn = wid >> 1;               // 2 m-warps x 4 n-warps
    int qrow = lane >> 2, qcol = lane & 3;

    float acc[2][5][4];
#pragma unroll
    for (int mt = 0; mt < 2; mt++)
#pragma unroll
        for (int nt = 0; nt < 5; nt++)
#pragma unroll
            for (int j = 0; j < 4; j++) acc[mt][nt][j] = 0.0f;

    auto compute = [&](int bw) {
#pragma unroll
        for (int ks = 0; ks < 2; ks++) {
            uint32_t bh[5][2], bl[5][2];
#pragma unroll
            for (int nt = 0; nt < 5; nt++) {
                int w = bw + W_BH + (wn * 40 + nt * 8 + qrow) * SROW + ks * 8 + qcol;
                bh[nt][0] = sm4[w]; bh[nt][1] = sm4[w + 4];
                bl[nt][0] = sm4[w + (W_BL - W_BH)]; bl[nt][1] = sm4[w + (W_BL - W_BH) + 4];
            }
#pragma unroll
            for (int mt = 0; mt < 2; mt++) {
                int w = bw + (wm * 32 + mt * 16 + qrow) * SROW + ks * 8 + qcol;
                uint32_t ah0 = sm4[w], ah1 = sm4[w + 8 * SROW];
                uint32_t ah2 = sm4[w + 4], ah3 = sm4[w + 8 * SROW + 4];
                uint32_t al0 = sm4[w + W_AL], al1 = sm4[w + W_AL + 8 * SROW];
                uint32_t al2 = sm4[w + W_AL + 4], al3 = sm4[w + W_AL + 8 * SROW + 4];
#pragma unroll
                for (int nt = 0; nt < 5; nt++) {
                    MMA_BF16(acc[mt][nt], ah0, ah1, ah2, ah3, bh[nt][0], bh[nt][1]);
                    MMA_BF16(acc[mt][nt], ah0, ah1, ah2, ah3, bl[nt][0], bl[nt][1]);
                    MMA_BF16(acc[mt][nt], al0, al1, al2, al3, bh[nt][0], bh[nt][1]);
                }
            }
        }
    };

    // Prologue: stage chunk 0 into buffer 0
    stageA(0, k0);
    if (mode == 1) stageB1(0, k0);
    CP_COMMIT();
    if (mode == 0) { prefB0(k0); stsB0(0); }
    CP_WAIT0();
    __syncthreads();

    // Pipelined main loop over 4 chunks
#pragma unroll
    for (int c = 0; c < 4; c++) {
        int bw = (c & 1) * W_BUF;
        int nw = W_BUF - bw;
        if (c < 3) {
            int kn = k0 + (c + 1) * 32;
            stageA(nw, kn);
            if (mode == 1) stageB1(nw, kn);
            CP_COMMIT();
            if (mode == 0) prefB0(kn);
        }
        compute(bw);
        if (c < 3) {
            if (mode == 0) stsB0(nw);
            CP_WAIT0();
            __syncthreads();
        }
    }

    // Epilogue
#pragma unroll
    for (int mt = 0; mt < 2; mt++) {
        int row = arow0 + wm * 32 + mt * 16 + qrow;
#pragma unroll
        for (int nt = 0; nt < 5; nt++) {
            int col = wn * 40 + nt * 8 + qcol * 2;
            *reinterpret_cast<float2*>(outp + (size_t)row * 160 + col) =
                make_float2(acc[mt][nt][0], acc[mt][nt][1]);
            *reinterpret_cast<float2*>(outp + (size_t)(row + 8) * 160 + col) =
                make_float2(acc[mt][nt][2], acc[mt][nt][3]);
        }
    }
}

// ---------------------------------------------------------------------------
// Split-K reduce stage 1 (float4): 72 -> 8 partials. grid (40,8) x 256.
__global__ void k_red1() {
    int e4 = blockIdx.x * 256 + threadIdx.x;       // < 10240
    int g = blockIdx.y;
    const float4* sp = reinterpret_cast<const float4*>(g_spart);
    float4 a = make_float4(0.f, 0.f, 0.f, 0.f);
#pragma unroll
    for (int p = 0; p < 9; p++) {
        float4 v = sp[(size_t)(g * 9 + p) * 10240 + e4];
        a.x += v.x; a.y += v.y; a.z += v.z; a.w += v.w;
    }
    reinterpret_cast<float4*>(g_spart2)[(size_t)g * 10240 + e4] = a;
}

// Stage 2 + squash (+ v^T bf16 split for the next M-GEMM). grid 40 x 256.
__global__ void k_red2(float* dst, int writeVT) {
    int t4 = blockIdx.x * 256 + threadIdx.x;       // < 10240
    const float4* sp = reinterpret_cast<const float4*>(g_spart2);
    float4 a = make_float4(0.f, 0.f, 0.f, 0.f);
#pragma unroll
    for (int p = 0; p < 8; p++) {
        float4 v = sp[(size_t)p * 10240 + t4];
        a.x += v.x; a.y += v.y; a.z += v.z; a.w += v.w;
    }
    float sq = a.x * a.x + a.y * a.y + a.z * a.z + a.w * a.w;
    sq += __shfl_xor_sync(0xffffffffu, sq, 1);     // 4 lanes = 16 u's
    sq += __shfl_xor_sync(0xffffffffu, sq, 2);
    float m = sq / ((1.0f + sq) * sqrtf(sq + 1e-9f));
    float4 v = make_float4(a.x * m, a.y * m, a.z * m, a.w * m);
    if (writeVT) {
        int elem0 = t4 * 4;
        int b = elem0 / 160, ou0 = elem0 - b * 160;
        float vv[4] = {v.x, v.y, v.z, v.w};
#pragma unroll
        for (int j = 0; j < 4; j++) {
            __nv_bfloat16 h = __float2bfloat16(vv[j]);
            size_t o = (size_t)(ou0 + j) * BATCH + b;
            g_vTh[o] = h;
            g_vTl[o] = __float2bfloat16(vv[j] - __bfloat162float(h));
        }
    } else {
        reinterpret_cast<float4*>(dst)[t4] = v;
    }
}

// ---------------------------------------------------------------------------
// b[i,o] += (1/B)*sum_{k,u} W[i][ou][k]*(m0+m1)[ik][ou]; fused softmax -> c.
__global__ __launch_bounds__(160) void k_bdot(const float* __restrict__ W) {
    __shared__ float so[10];
    int i = blockIdx.x;
    int t = threadIdx.x;                            // = ou
    const float4* Wp = reinterpret_cast<const float4*>(W + (size_t)i * 1280 + t * 8);
    float4 w0 = __ldg(Wp), w1 = __ldg(Wp + 1);
    float wk[8] = {w0.x, w0.y, w0.z, w0.w, w1.x, w1.y, w1.z, w1.w};
    const float* mp = g_mpart + (size_t)(i * 8) * 160 + t;
    float acc = 0.0f;
#pragma unroll
    for (int k = 0; k < 8; k++)
        acc += wk[k] * (__ldg(mp + k * 160) + __ldg(mp + MO + k * 160));
#pragma unroll
    for (int off = 8; off; off >>= 1) acc += __shfl_xor_sync(0xffffffffu, acc, off, 16);
    if ((t & 15) == 0) so[t >> 4] = acc;
    __syncthreads();
    float bn = -1e30f;
    if (t < 10) {
        bn = g_blog[i * 10 + t] + so[t] * (1.0f / BATCH);
        g_blog[i * 10 + t] = bn;
    }
    float m = bn;
#pragma unroll
    for (int off = 8; off; off >>= 1) m = fmaxf(m, __shfl_xor_sync(0xffffffffu, m, off, 16));
    float e = (t < 10) ? __expf(bn - m) : 0.0f;
    float s = e;
#pragma unroll
    for (int off = 8; off; off >>= 1) s += __shfl_xor_sync(0xffffffffu, s, off, 16);
    if (t < 10) g_c[i * 10 + t] = e / s;
}

// ---------------------------------------------------------------------------
extern "C" void kernel_launch(void* const* d_in, const int* in_sizes, int n_in,
                              void* d_out, int out_size) {
    const float* inp = (const float*)d_in[0];
    const float* W   = (const float*)d_in[1];
    if (in_sizes[0] == IN_CH * OUT_CH * OUT_U * 8) {       // defensive order check
        W = (const float*)d_in[0];
        inp = (const float*)d_in[1];
    }
    float* out = (float*)d_out;

    cudaFuncSetAttribute(k_mma, cudaFuncAttributeMaxDynamicSharedMemorySize, SM_TOTAL);

    dim3 gs(KSPLIT, 4), gm(144, 2), gt(NIK / 32, BATCH / 32), gr1(40, 8);

    k_init<<<45, 256>>>();
    k_splitW<<<MO / 256, 256>>>(W);
    k_split_x<<<gt, 256>>>(inp);
    // epoch 1 (c = 0.1 uniform via g_c init)
    k_mma<<<gs, 256, SM_TOTAL>>>(0);
    k_red1<<<gr1, 256>>>();
    k_red2<<<40, 256>>>(nullptr, 1);                       // v0 -> vT
    k_mma<<<gm, 256, SM_TOTAL>>>(1);
    k_bdot<<<IN_CH, 160>>>(W);                             // b1, c1
    // epoch 2
    k_mma<<<gs, 256, SM_TOTAL>>>(0);
    k_red1<<<gr1, 256>>>();
    k_red2<<<40, 256>>>(nullptr, 1);                       // v1 -> vT
    k_mma<<<gm, 256, SM_TOTAL>>>(1);
    k_bdot<<<IN_CH, 160>>>(W);                             // b2, c2
    // epoch 3
    k_mma<<<gs, 256, SM_TOTAL>>>(0);
    k_red1<<<gr1, 256>>>();
    k_red2<<<40, 256>>>(out, 0);                           // v2 -> output
}

// round 13
// speedup vs baseline: 1.0216x; 1.0216x over previous
#include <cuda_runtime.h>
#include <cuda_bf16.h>
#include <math.h>
#include <cstdint>

// ---------------------------------------------------------------------------
// Problem constants
#define BATCH   256
#define IN_CH   1152
#define OUT_CH  10
#define OUT_U   16
#define NIK     9216             // IN_CH*8, contraction dim for s-GEMM
#define OUD     160              // OUT_CH*OUT_U
#define KSPLIT  72
#define SOUT    40960            // BATCH*OUD
#define MO      (NIK*OUD)        // 1474560

// ---------------------------------------------------------------------------
// Device scratch (allocation-free)
__device__ __align__(16) __nv_bfloat16 g_xh[BATCH * NIK], g_xl[BATCH * NIK];   // x split  [b][ik]
__device__ __align__(16) __nv_bfloat16 g_xTh[NIK * BATCH], g_xTl[NIK * BATCH]; // x^T split[ik][b]
__device__ __align__(16) __nv_bfloat16 g_Wsh[MO], g_Wsl[MO];                   // W split [ou][ik]
__device__ __align__(16) __nv_bfloat16 g_Bch[MO], g_Bcl[MO];                   // (c∘W) split [ou][ik]
__device__ __align__(16) __nv_bfloat16 g_vTh[OUD * BATCH], g_vTl[OUD * BATCH]; // v^T split [ou][b]
__device__ __align__(16) float g_spart[KSPLIT * SOUT];   // s split-K partials
__device__ __align__(16) float g_spart2[8 * SOUT];       // stage-1 reduced
__device__ __align__(16) float g_mpart[2 * MO];          // M = x^T v, 2 halves
__device__ float g_blog[IN_CH * OUT_CH];
__device__ float g_c[IN_CH * OUT_CH];

// ---------------------------------------------------------------------------
#define MMA_BF16(c, A0, A1, A2, A3, B0, B1)                                   \
    asm volatile("mma.sync.aligned.m16n8k16.row.col.f32.bf16.bf16.f32 "       \
                 "{%0,%1,%2,%3}, {%4,%5,%6,%7}, {%8,%9}, {%0,%1,%2,%3};"      \
                 : "+f"((c)[0]), "+f"((c)[1]), "+f"((c)[2]), "+f"((c)[3])     \
                 : "r"(A0), "r"(A1), "r"(A2), "r"(A3), "r"(B0), "r"(B1))

__device__ __forceinline__ uint32_t smem_u32(const void* p) {
    uint32_t a;
    asm("{ .reg .u64 t; cvta.to.shared.u64 t, %1; cvt.u32.u64 %0, t; }" : "=r"(a) : "l"(p));
    return a;
}
__device__ __forceinline__ void cpa16(uint32_t dst, const void* src) {
    asm volatile("cp.async.cg.shared.global [%0], [%1], 16;" :: "r"(dst), "l"(src));
}
#define CP_COMMIT() asm volatile("cp.async.commit_group;" ::: "memory")
#define CP_WAIT0()  asm volatile("cp.async.wait_group 0;" ::: "memory")

// SMEM word layout (u32), row stride 68 words (68 mod 32 = 4 ->
// fragment loads bank = (4r + c) mod 32, conflict-free; 272B rows are 16B-aligned)
#define ROWW 68
#define WA_H 0
#define WA_L 8704                      // 128*68
#define WB_H 17408
#define WB_L 28288                     // +160*68
#define SM_TOTAL 156672                // (28288+160*68)*4 bytes

// ---------------------------------------------------------------------------
__global__ void k_init() {
    int t = blockIdx.x * 256 + threadIdx.x;
    if (t < IN_CH * OUT_CH) { g_blog[t] = 0.0f; g_c[t] = 0.1f; }
}

// One-time W -> bf16 hi/lo split in [ou][ik] layout (output-coalesced).
__global__ void k_splitW(const float* __restrict__ W) {
    int idx = blockIdx.x * 256 + threadIdx.x;     // < MO, = ou*NIK+ik
    int ou = idx / NIK, ik = idx - ou * NIK;
    float f = __ldg(&W[(size_t)(ik >> 3) * 1280 + ou * 8 + (ik & 7)]);
    __nv_bfloat16 h = __float2bfloat16(f);
    g_Wsh[idx] = h;
    g_Wsl[idx] = __float2bfloat16(f - __bfloat162float(h));
}

// x -> bf16 hi/lo split in BOTH [b][ik] and [ik][b] layouts (single x read).
__global__ void k_split_x(const float* __restrict__ x) {
    __shared__ float s[32][33];
    int ik0 = blockIdx.x * 32, b0 = blockIdx.y * 32;
    int t = threadIdx.x, tr = t >> 5, tc = t & 31;
#pragma unroll
    for (int j = 0; j < 4; j++)
        s[tr + 8 * j][tc] = x[(size_t)(b0 + tr + 8 * j) * NIK + ik0 + tc];
    __syncthreads();
#pragma unroll
    for (int j = 0; j < 4; j++) {
        int r = tr + 8 * j;
        float f = s[r][tc];
        __nv_bfloat16 h = __float2bfloat16(f);
        size_t o = (size_t)(b0 + r) * NIK + ik0 + tc;
        g_xh[o] = h;
        g_xl[o] = __float2bfloat16(f - __bfloat162float(h));
        float ft = s[tc][r];
        __nv_bfloat16 h2 = __float2bfloat16(ft);
        size_t o2 = (size_t)(ik0 + r) * BATCH + b0 + tc;
        g_xTh[o2] = h2;
        g_xTl[o2] = __float2bfloat16(ft - __bfloat162float(h2));
    }
}

// ---------------------------------------------------------------------------
// Lean per-epoch Bc = c∘W (bf16 in -> bf16 hi/lo out). 8 elems (one i) per thread.
__global__ void k_makeB() {
    int idx = blockIdx.x * 256 + threadIdx.x;      // < MO/8 = 184320
    int ou = idx / 1152, i = idx - ou * 1152;      // NIK/8 = 1152
    float c = __ldg(&g_c[i * 10 + (ou >> 4)]);
    size_t g = (size_t)ou * NIK + i * 8;
    uint4 h4 = *reinterpret_cast<const uint4*>(g_Wsh + g);
    uint4 l4 = *reinterpret_cast<const uint4*>(g_Wsl + g);
    uint32_t hw[4] = {h4.x, h4.y, h4.z, h4.w};
    uint32_t lw[4] = {l4.x, l4.y, l4.z, l4.w};
    uint32_t oh[4], ol[4];
#pragma unroll
    for (int q = 0; q < 4; q++) {
        float2 fh = __bfloat1622float2(*reinterpret_cast<__nv_bfloat162*>(&hw[q]));
        float2 fl = __bfloat1622float2(*reinterpret_cast<__nv_bfloat162*>(&lw[q]));
        float f0 = c * (fh.x + fl.x), f1 = c * (fh.y + fl.y);
        __nv_bfloat162 nh = __floats2bfloat162_rn(f0, f1);
        float2 nhf = __bfloat1622float2(nh);
        __nv_bfloat162 nl = __floats2bfloat162_rn(f0 - nhf.x, f1 - nhf.y);
        oh[q] = *reinterpret_cast<uint32_t*>(&nh);
        ol[q] = *reinterpret_cast<uint32_t*>(&nl);
    }
    *reinterpret_cast<uint4*>(g_Bch + g) = make_uint4(oh[0], oh[1], oh[2], oh[3]);
    *reinterpret_cast<uint4*>(g_Bcl + g) = make_uint4(ol[0], ol[1], ol[2], ol[3]);
}

// ---------------------------------------------------------------------------
// Monolithic warp-MMA GEMM: D[128 x 160] = A[128 x 128k] · B[160 x 128k]^T.
// Unified operand staging via cp.async (no in-kernel conversion). bf16x3.
// mode 0 (s-GEMM): A=x[b][ik],  B=Bc[ou][ik].  grid (72,2)
// mode 1 (M-GEMM): A=xT[ik][b], B=vT[ou][b].   grid (72,2) [bx=ikblk, by=bs]
__global__ __launch_bounds__(256) void k_mma(int mode) {
    extern __shared__ uint32_t sm4[];
    uint32_t smb = smem_u32(sm4);
    int t = threadIdx.x;

    const __nv_bfloat16 *Ah_g, *Al_g, *Bh_g, *Bl_g;
    int astr, bstr, arow0, k0;
    float* outp;
    if (mode == 0) {
        Ah_g = g_xh;  Al_g = g_xl;  astr = NIK;   arow0 = blockIdx.y * 128;
        Bh_g = g_Bch; Bl_g = g_Bcl; bstr = NIK;   k0 = blockIdx.x * 128;
        outp = g_spart + (size_t)blockIdx.x * SOUT;
    } else {
        Ah_g = g_xTh; Al_g = g_xTl; astr = BATCH; arow0 = blockIdx.x * 128;
        Bh_g = g_vTh; Bl_g = g_vTl; bstr = BATCH; k0 = blockIdx.y * 128;
        outp = g_mpart + (size_t)blockIdx.y * MO;
    }

    // Stage A (128 x 128 bf16 hi+lo) via cp.async
#pragma unroll
    for (int it = 0; it < 8; it++) {
        int idx = t + 256 * it, r = idx >> 4, seg = idx & 15;
        size_t g = (size_t)(arow0 + r) * astr + k0 + seg * 8;
        uint32_t d = smb + (WA_H + r * ROWW + seg * 4) * 4;
        cpa16(d, Ah_g + g);
        cpa16(d + WA_L * 4, Al_g + g);
    }
    // Stage B (160 x 128 bf16 hi+lo) via cp.async
#pragma unroll
    for (int it = 0; it < 10; it++) {
        int idx = t + 256 * it, r = idx >> 4, seg = idx & 15;
        size_t g = (size_t)r * bstr + k0 + seg * 8;
        uint32_t d = smb + (WB_H + r * ROWW + seg * 4) * 4;
        cpa16(d, Bh_g + g);
        cpa16(d + (WB_L - WB_H) * 4, Bl_g + g);
    }
    CP_COMMIT();
    CP_WAIT0();
    __syncthreads();

    int wid = t >> 5, lane = t & 31;
    int wm = wid & 3, wn = wid >> 2;               // 4 m-warps x 2 n-warps
    int qrow = lane >> 2, qcol = lane & 3;

    float acc[2][10][4];
#pragma unroll
    for (int mt = 0; mt < 2; mt++)
#pragma unroll
        for (int nt = 0; nt < 10; nt++)
#pragma unroll
            for (int j = 0; j < 4; j++) acc[mt][nt][j] = 0.0f;

#pragma unroll
    for (int ks = 0; ks < 8; ks++) {
        uint32_t bh[10][2], bl[10][2];
#pragma unroll
        for (int nt = 0; nt < 10; nt++) {
            int w = WB_H + (wn * 80 + nt * 8 + qrow) * ROWW + ks * 8 + qcol;
            bh[nt][0] = sm4[w]; bh[nt][1] = sm4[w + 4];
            bl[nt][0] = sm4[w + (WB_L - WB_H)]; bl[nt][1] = sm4[w + (WB_L - WB_H) + 4];
        }
#pragma unroll
        for (int mt = 0; mt < 2; mt++) {
            int w = WA_H + (wm * 32 + mt * 16 + qrow) * ROWW + ks * 8 + qcol;
            uint32_t ah0 = sm4[w], ah1 = sm4[w + 8 * ROWW];
            uint32_t ah2 = sm4[w + 4], ah3 = sm4[w + 8 * ROWW + 4];
            uint32_t al0 = sm4[w + WA_L], al1 = sm4[w + WA_L + 8 * ROWW];
            uint32_t al2 = sm4[w + WA_L + 4], al3 = sm4[w + WA_L + 8 * ROWW + 4];
#pragma unroll
            for (int nt = 0; nt < 10; nt++) {
                MMA_BF16(acc[mt][nt], ah0, ah1, ah2, ah3, bh[nt][0], bh[nt][1]); // hi*hi
                MMA_BF16(acc[mt][nt], ah0, ah1, ah2, ah3, bl[nt][0], bl[nt][1]); // hi*lo
                MMA_BF16(acc[mt][nt], al0, al1, al2, al3, bh[nt][0], bh[nt][1]); // lo*hi
            }
        }
    }

#pragma unroll
    for (int mt = 0; mt < 2; mt++) {
        int row = arow0 + wm * 32 + mt * 16 + qrow;
#pragma unroll
        for (int nt = 0; nt < 10; nt++) {
            int col = wn * 80 + nt * 8 + qcol * 2;
            *reinterpret_cast<float2*>(outp + (size_t)row * 160 + col) =
                make_float2(acc[mt][nt][0], acc[mt][nt][1]);
            *reinterpret_cast<float2*>(outp + (size_t)(row + 8) * 160 + col) =
                make_float2(acc[mt][nt][2], acc[mt][nt][3]);
        }
    }
}

// ---------------------------------------------------------------------------
// Split-K reduce stage 1 (float4): 72 -> 8 partials. grid (40,8) x 256.
__global__ void k_red1() {
    int e4 = blockIdx.x * 256 + threadIdx.x;       // < 10240
    int g = blockIdx.y;
    const float4* sp = reinterpret_cast<const float4*>(g_spart);
    float4 a = make_float4(0.f, 0.f, 0.f, 0.f);
#pragma unroll
    for (int p = 0; p < 9; p++) {
        float4 v = sp[(size_t)(g * 9 + p) * 10240 + e4];
        a.x += v.x; a.y += v.y; a.z += v.z; a.w += v.w;
    }
    reinterpret_cast<float4*>(g_spart2)[(size_t)g * 10240 + e4] = a;
}

// Stage 2 + squash (+ v^T bf16 split for the next M-GEMM). grid 40 x 256.
__global__ void k_red2(float* dst, int writeVT) {
    int t4 = blockIdx.x * 256 + threadIdx.x;       // < 10240
    const float4* sp = reinterpret_cast<const float4*>(g_spart2);
    float4 a = make_float4(0.f, 0.f, 0.f, 0.f);
#pragma unroll
    for (int p = 0; p < 8; p++) {
        float4 v = sp[(size_t)p * 10240 + t4];
        a.x += v.x; a.y += v.y; a.z += v.z; a.w += v.w;
    }
    float sq = a.x * a.x + a.y * a.y + a.z * a.z + a.w * a.w;
    sq += __shfl_xor_sync(0xffffffffu, sq, 1);     // 4 lanes = 16 u's
    sq += __shfl_xor_sync(0xffffffffu, sq, 2);
    float m = sq / ((1.0f + sq) * sqrtf(sq + 1e-9f));
    float4 v = make_float4(a.x * m, a.y * m, a.z * m, a.w * m);
    if (writeVT) {
        int elem0 = t4 * 4;
        int b = elem0 / 160, ou0 = elem0 - b * 160;
        float vv[4] = {v.x, v.y, v.z, v.w};
#pragma unroll
        for (int j = 0; j < 4; j++) {
            __nv_bfloat16 h = __float2bfloat16(vv[j]);
            size_t o = (size_t)(ou0 + j) * BATCH + b;
            g_vTh[o] = h;
            g_vTl[o] = __float2bfloat16(vv[j] - __bfloat162float(h));
        }
    } else {
        reinterpret_cast<float4*>(dst)[t4] = v;
    }
}

// ---------------------------------------------------------------------------
// b[i,o] += (1/B)*sum_{k,u} W[i][ou][k]*(m0+m1)[ik][ou]; fused softmax -> c.
__global__ __launch_bounds__(160) void k_bdot(const float* __restrict__ W) {
    __shared__ float so[10];
    int i = blockIdx.x;
    int t = threadIdx.x;                            // = ou
    const float4* Wp = reinterpret_cast<const float4*>(W + (size_t)i * 1280 + t * 8);
    float4 w0 = __ldg(Wp), w1 = __ldg(Wp + 1);
    float wk[8] = {w0.x, w0.y, w0.z, w0.w, w1.x, w1.y, w1.z, w1.w};
    const float* mp = g_mpart + (size_t)(i * 8) * 160 + t;
    float acc = 0.0f;
#pragma unroll
    for (int k = 0; k < 8; k++)
        acc += wk[k] * (__ldg(mp + k * 160) + __ldg(mp + MO + k * 160));
#pragma unroll
    for (int off = 8; off; off >>= 1) acc += __shfl_xor_sync(0xffffffffu, acc, off, 16);
    if ((t & 15) == 0) so[t >> 4] = acc;
    __syncthreads();
    float bn = -1e30f;
    if (t < 10) {
        bn = g_blog[i * 10 + t] + so[t] * (1.0f / BATCH);
        g_blog[i * 10 + t] = bn;
    }
    float m = bn;
#pragma unroll
    for (int off = 8; off; off >>= 1) m = fmaxf(m, __shfl_xor_sync(0xffffffffu, m, off, 16));
    float e = (t < 10) ? __expf(bn - m) : 0.0f;
    float s = e;
#pragma unroll
    for (int off = 8; off; off >>= 1) s += __shfl_xor_sync(0xffffffffu, s, off, 16);
    if (t < 10) g_c[i * 10 + t] = e / s;
}

// ---------------------------------------------------------------------------
extern "C" void kernel_launch(void* const* d_in, const int* in_sizes, int n_in,
                              void* d_out, int out_size) {
    const float* inp = (const float*)d_in[0];
    const float* W   = (const float*)d_in[1];
    if (in_sizes[0] == IN_CH * OUT_CH * OUT_U * 8) {       // defensive order check
        W = (const float*)d_in[0];
        inp = (const float*)d_in[1];
    }
    float* out = (float*)d_out;

    cudaFuncSetAttribute(k_mma, cudaFuncAttributeMaxDynamicSharedMemorySize, SM_TOTAL);

    dim3 gg(KSPLIT, 2), gt(NIK / 32, BATCH / 32), gr1(40, 8);

    k_init<<<45, 256>>>();
    k_splitW<<<MO / 256, 256>>>(W);
    k_split_x<<<gt, 256>>>(inp);
    // epoch 1 (c = 0.1 uniform via g_c init)
    k_makeB<<<720, 256>>>();
    k_mma<<<gg, 256, SM_TOTAL>>>(0);
    k_red1<<<gr1, 256>>>();
    k_red2<<<40, 256>>>(nullptr, 1);                       // v0 -> vT
    k_mma<<<gg, 256, SM_TOTAL>>>(1);
    k_bdot<<<IN_CH, 160>>>(W);                             // b1, c1
    // epoch 2
    k_makeB<<<720, 256>>>();
    k_mma<<<gg, 256, SM_TOTAL>>>(0);
    k_red1<<<gr1, 256>>>();
    k_red2<<<40, 256>>>(nullptr, 1);                       // v1 -> vT
    k_mma<<<gg, 256, SM_TOTAL>>>(1);
    k_bdot<<<IN_CH, 160>>>(W);                             // b2, c2
    // epoch 3
    k_makeB<<<720, 256>>>();
    k_mma<<<gg, 256, SM_TOTAL>>>(0);
    k_red1<<<gr1, 256>>>();
    k_red2<<<40, 256>>>(out, 0);                           // v2 -> output
}

// round 14
// speedup vs baseline: 1.0767x; 1.0540x over previous
#include <cuda_runtime.h>
#include <cuda_bf16.h>
#include <math.h>
#include <cstdint>

// ---------------------------------------------------------------------------
// Problem constants
#define BATCH   256
#define IN_CH   1152
#define OUT_CH  10
#define OUT_U   16
#define NIK     9216             // IN_CH*8, contraction dim for s-GEMM
#define OUD     160              // OUT_CH*OUT_U
#define KSPLIT  72
#define SOUT    40960            // BATCH*OUD
#define MO      (NIK*OUD)        // 1474560

// ---------------------------------------------------------------------------
// Device scratch (allocation-free)
__device__ __align__(16) __nv_bfloat16 g_xh[BATCH * NIK], g_xl[BATCH * NIK];   // x split  [b][ik]
__device__ __align__(16) __nv_bfloat16 g_xTh[NIK * BATCH], g_xTl[NIK * BATCH]; // x^T split[ik][b]
__device__ __align__(16) __nv_bfloat16 g_Bch[MO], g_Bcl[MO];                   // (c∘W) split [ou][ik]
__device__ __align__(16) __nv_bfloat16 g_vTh[OUD * BATCH], g_vTl[OUD * BATCH]; // v^T split [ou][b]
__device__ __align__(16) float g_spart[KSPLIT * SOUT];   // s split-K partials
__device__ __align__(16) float g_spart2[8 * SOUT];       // stage-1 reduced
__device__ __align__(16) float g_mpart[2 * MO];          // M = x^T v, 2 halves
__device__ float g_blog[IN_CH * OUT_CH];                 // routing logits

// ---------------------------------------------------------------------------
#define MMA_BF16(c, A0, A1, A2, A3, B0, B1)                                   \
    asm volatile("mma.sync.aligned.m16n8k16.row.col.f32.bf16.bf16.f32 "       \
                 "{%0,%1,%2,%3}, {%4,%5,%6,%7}, {%8,%9}, {%0,%1,%2,%3};"      \
                 : "+f"((c)[0]), "+f"((c)[1]), "+f"((c)[2]), "+f"((c)[3])     \
                 : "r"(A0), "r"(A1), "r"(A2), "r"(A3), "r"(B0), "r"(B1))

// SMEM word layout (u32), row stride 68 words (68 mod 32 = 4 ->
// fragment loads bank = (4r + c) mod 32, conflict-free; 272B rows 16B-aligned)
#define ROWW 68
#define WA_H 0
#define WA_L 8704                      // 128*68
#define WB_H 17408
#define WB_L 28288                     // +160*68
#define SM_TOTAL 156672                // (28288+160*68)*4 bytes

// ---------------------------------------------------------------------------
// One-time: Bc = bf16 hi/lo split of 0.1*W in [ou][ik] layout (epoch-1 c=0.1),
// plus routing-logit zeroing (per replay). W_split arrays no longer needed.
__global__ void k_splitW(const float* __restrict__ W) {
    int idx = blockIdx.x * 256 + threadIdx.x;     // < MO, = ou*NIK+ik
    int ou = idx / NIK, ik = idx - ou * NIK;
    float f = 0.1f * __ldg(&W[(size_t)(ik >> 3) * 1280 + ou * 8 + (ik & 7)]);
    __nv_bfloat16 h = __float2bfloat16(f);
    g_Bch[idx] = h;
    g_Bcl[idx] = __float2bfloat16(f - __bfloat162float(h));
    if (idx < IN_CH * OUT_CH) g_blog[idx] = 0.0f;
}

// x -> bf16 hi/lo split in BOTH [b][ik] and [ik][b] layouts (single x read).
__global__ void k_split_x(const float* __restrict__ x) {
    __shared__ float s[32][33];
    int ik0 = blockIdx.x * 32, b0 = blockIdx.y * 32;
    int t = threadIdx.x, tr = t >> 5, tc = t & 31;
#pragma unroll
    for (int j = 0; j < 4; j++)
        s[tr + 8 * j][tc] = x[(size_t)(b0 + tr + 8 * j) * NIK + ik0 + tc];
    __syncthreads();
#pragma unroll
    for (int j = 0; j < 4; j++) {
        int r = tr + 8 * j;
        float f = s[r][tc];
        __nv_bfloat16 h = __float2bfloat16(f);
        size_t o = (size_t)(b0 + r) * NIK + ik0 + tc;
        g_xh[o] = h;
        g_xl[o] = __float2bfloat16(f - __bfloat162float(h));
        float ft = s[tc][r];
        __nv_bfloat16 h2 = __float2bfloat16(ft);
        size_t o2 = (size_t)(ik0 + r) * BATCH + b0 + tc;
        g_xTh[o2] = h2;
        g_xTl[o2] = __float2bfloat16(ft - __bfloat162float(h2));
    }
}

// ---------------------------------------------------------------------------
// Monolithic warp-MMA GEMM: D[128 x 160] = A[128 x 128k] · B[160 x 128k]^T.
// Plain LDG->STS staging (R10-proven), no in-kernel conversion. bf16x3.
// mode 0 (s-GEMM): A=x[b][ik],  B=Bc[ou][ik].  grid (72,2)
// mode 1 (M-GEMM): A=xT[ik][b], B=vT[ou][b].   grid (72,2) [bx=ikblk, by=bs]
__global__ __launch_bounds__(256) void k_mma(int mode) {
    extern __shared__ uint32_t sm4[];
    int t = threadIdx.x;

    const __nv_bfloat16 *Ah_g, *Al_g, *Bh_g, *Bl_g;
    int astr, bstr, arow0, k0;
    float* outp;
    if (mode == 0) {
        Ah_g = g_xh;  Al_g = g_xl;  astr = NIK;   arow0 = blockIdx.y * 128;
        Bh_g = g_Bch; Bl_g = g_Bcl; bstr = NIK;   k0 = blockIdx.x * 128;
        outp = g_spart + (size_t)blockIdx.x * SOUT;
    } else {
        Ah_g = g_xTh; Al_g = g_xTl; astr = BATCH; arow0 = blockIdx.x * 128;
        Bh_g = g_vTh; Bl_g = g_vTl; bstr = BATCH; k0 = blockIdx.y * 128;
        outp = g_mpart + (size_t)blockIdx.y * MO;
    }

    // Stage A (128 x 128 bf16 hi+lo)
#pragma unroll
    for (int it = 0; it < 8; it++) {
        int idx = t + 256 * it, r = idx >> 4, seg = idx & 15;
        size_t g = (size_t)(arow0 + r) * astr + k0 + seg * 8;
        *reinterpret_cast<uint4*>(sm4 + WA_H + r * ROWW + seg * 4) =
            *reinterpret_cast<const uint4*>(Ah_g + g);
        *reinterpret_cast<uint4*>(sm4 + WA_L + r * ROWW + seg * 4) =
            *reinterpret_cast<const uint4*>(Al_g + g);
    }
    // Stage B (160 x 128 bf16 hi+lo)
#pragma unroll
    for (int it = 0; it < 10; it++) {
        int idx = t + 256 * it, r = idx >> 4, seg = idx & 15;
        size_t g = (size_t)r * bstr + k0 + seg * 8;
        *reinterpret_cast<uint4*>(sm4 + WB_H + r * ROWW + seg * 4) =
            *reinterpret_cast<const uint4*>(Bh_g + g);
        *reinterpret_cast<uint4*>(sm4 + WB_L + r * ROWW + seg * 4) =
            *reinterpret_cast<const uint4*>(Bl_g + g);
    }
    __syncthreads();

    int wid = t >> 5, lane = t & 31;
    int wm = wid & 3, wn = wid >> 2;               // 4 m-warps x 2 n-warps
    int qrow = lane >> 2, qcol = lane & 3;

    float acc[2][10][4];
#pragma unroll
    for (int mt = 0; mt < 2; mt++)
#pragma unroll
        for (int nt = 0; nt < 10; nt++)
#pragma unroll
            for (int j = 0; j < 4; j++) acc[mt][nt][j] = 0.0f;

#pragma unroll
    for (int ks = 0; ks < 8; ks++) {
        uint32_t bh[10][2], bl[10][2];
#pragma unroll
        for (int nt = 0; nt < 10; nt++) {
            int w = WB_H + (wn * 80 + nt * 8 + qrow) * ROWW + ks * 8 + qcol;
            bh[nt][0] = sm4[w]; bh[nt][1] = sm4[w + 4];
            bl[nt][0] = sm4[w + (WB_L - WB_H)]; bl[nt][1] = sm4[w + (WB_L - WB_H) + 4];
        }
#pragma unroll
        for (int mt = 0; mt < 2; mt++) {
            int w = WA_H + (wm * 32 + mt * 16 + qrow) * ROWW + ks * 8 + qcol;
            uint32_t ah0 = sm4[w], ah1 = sm4[w + 8 * ROWW];
            uint32_t ah2 = sm4[w + 4], ah3 = sm4[w + 8 * ROWW + 4];
            uint32_t al0 = sm4[w + WA_L], al1 = sm4[w + WA_L + 8 * ROWW];
            uint32_t al2 = sm4[w + WA_L + 4], al3 = sm4[w + WA_L + 8 * ROWW + 4];
#pragma unroll
            for (int nt = 0; nt < 10; nt++) {
                MMA_BF16(acc[mt][nt], ah0, ah1, ah2, ah3, bh[nt][0], bh[nt][1]); // hi*hi
                MMA_BF16(acc[mt][nt], ah0, ah1, ah2, ah3, bl[nt][0], bl[nt][1]); // hi*lo
                MMA_BF16(acc[mt][nt], al0, al1, al2, al3, bh[nt][0], bh[nt][1]); // lo*hi
            }
        }
    }

#pragma unroll
    for (int mt = 0; mt < 2; mt++) {
        int row = arow0 + wm * 32 + mt * 16 + qrow;
#pragma unroll
        for (int nt = 0; nt < 10; nt++) {
            int col = wn * 80 + nt * 8 + qcol * 2;
            *reinterpret_cast<float2*>(outp + (size_t)row * 160 + col) =
                make_float2(acc[mt][nt][0], acc[mt][nt][1]);
            *reinterpret_cast<float2*>(outp + (size_t)(row + 8) * 160 + col) =
                make_float2(acc[mt][nt][2], acc[mt][nt][3]);
        }
    }
}

// ---------------------------------------------------------------------------
// Split-K reduce stage 1 (float4): 72 -> 8 partials. grid (40,8) x 256.
__global__ void k_red1() {
    int e4 = blockIdx.x * 256 + threadIdx.x;       // < 10240
    int g = blockIdx.y;
    const float4* sp = reinterpret_cast<const float4*>(g_spart);
    float4 a = make_float4(0.f, 0.f, 0.f, 0.f);
#pragma unroll
    for (int p = 0; p < 9; p++) {
        float4 v = sp[(size_t)(g * 9 + p) * 10240 + e4];
        a.x += v.x; a.y += v.y; a.z += v.z; a.w += v.w;
    }
    reinterpret_cast<float4*>(g_spart2)[(size_t)g * 10240 + e4] = a;
}

// Stage 2 + squash (+ v^T bf16 split for the next M-GEMM). grid 40 x 256.
__global__ void k_red2(float* dst, int writeVT) {
    int t4 = blockIdx.x * 256 + threadIdx.x;       // < 10240
    const float4* sp = reinterpret_cast<const float4*>(g_spart2);
    float4 a = make_float4(0.f, 0.f, 0.f, 0.f);
#pragma unroll
    for (int p = 0; p < 8; p++) {
        float4 v = sp[(size_t)p * 10240 + t4];
        a.x += v.x; a.y += v.y; a.z += v.z; a.w += v.w;
    }
    float sq = a.x * a.x + a.y * a.y + a.z * a.z + a.w * a.w;
    sq += __shfl_xor_sync(0xffffffffu, sq, 1);     // 4 lanes = 16 u's
    sq += __shfl_xor_sync(0xffffffffu, sq, 2);
    float m = sq / ((1.0f + sq) * sqrtf(sq + 1e-9f));
    float4 v = make_float4(a.x * m, a.y * m, a.z * m, a.w * m);
    if (writeVT) {
        int elem0 = t4 * 4;
        int b = elem0 / 160, ou0 = elem0 - b * 160;
        float vv[4] = {v.x, v.y, v.z, v.w};
#pragma unroll
        for (int j = 0; j < 4; j++) {
            __nv_bfloat16 h = __float2bfloat16(vv[j]);
            size_t o = (size_t)(ou0 + j) * BATCH + b;
            g_vTh[o] = h;
            g_vTl[o] = __float2bfloat16(vv[j] - __bfloat162float(h));
        }
    } else {
        reinterpret_cast<float4*>(dst)[t4] = v;
    }
}

// ---------------------------------------------------------------------------
// b[i,o] += (1/B)*sum_{k,u} W[i][ou][k]*(m0+m1)[ik][ou]; fused softmax AND
// fused next-epoch Bc = c∘W bf16 hi/lo write (c and W already in registers).
// Block per input capsule i, thread per ou (160 threads).
__global__ __launch_bounds__(160) void k_bdot(const float* __restrict__ W) {
    __shared__ float so[10];
    __shared__ float sb[10];
    int i = blockIdx.x;
    int t = threadIdx.x;                            // = ou
    const float4* Wp = reinterpret_cast<const float4*>(W + (size_t)i * 1280 + t * 8);
    float4 w0 = __ldg(Wp), w1 = __ldg(Wp + 1);
    float wk[8] = {w0.x, w0.y, w0.z, w0.w, w1.x, w1.y, w1.z, w1.w};
    const float* mp = g_mpart + (size_t)(i * 8) * 160 + t;
    float acc = 0.0f;
#pragma unroll
    for (int k = 0; k < 8; k++)
        acc += wk[k] * (__ldg(mp + k * 160) + __ldg(mp + MO + k * 160));
#pragma unroll
    for (int off = 8; off; off >>= 1) acc += __shfl_xor_sync(0xffffffffu, acc, off, 16);
    if ((t & 15) == 0) so[t >> 4] = acc;
    __syncthreads();
    if (t < 10) {
        float bn = g_blog[i * 10 + t] + so[t] * (1.0f / BATCH);
        g_blog[i * 10 + t] = bn;
        sb[t] = bn;
    }
    __syncthreads();
    // Every thread computes its own softmax over the 10 logits.
    float m = sb[0];
#pragma unroll
    for (int o = 1; o < 10; o++) m = fmaxf(m, sb[o]);
    float sum = 0.0f;
#pragma unroll
    for (int o = 0; o < 10; o++) sum += __expf(sb[o] - m);
    float c = __expf(sb[t >> 4] - m) / sum;
    // Write Bc[ou][i*8..i*8+7] hi/lo (next epoch's s-GEMM B operand).
    uint32_t oh[4], ol[4];
#pragma unroll
    for (int q = 0; q < 4; q++) {
        float f0 = c * wk[2 * q], f1 = c * wk[2 * q + 1];
        __nv_bfloat162 nh = __floats2bfloat162_rn(f0, f1);
        float2 nhf = __bfloat1622float2(nh);
        __nv_bfloat162 nl = __floats2bfloat162_rn(f0 - nhf.x, f1 - nhf.y);
        oh[q] = *reinterpret_cast<uint32_t*>(&nh);
        ol[q] = *reinterpret_cast<uint32_t*>(&nl);
    }
    size_t g = (size_t)t * NIK + i * 8;
    *reinterpret_cast<uint4*>(g_Bch + g) = make_uint4(oh[0], oh[1], oh[2], oh[3]);
    *reinterpret_cast<uint4*>(g_Bcl + g) = make_uint4(ol[0], ol[1], ol[2], ol[3]);
}

// ---------------------------------------------------------------------------
extern "C" void kernel_launch(void* const* d_in, const int* in_sizes, int n_in,
                              void* d_out, int out_size) {
    const float* inp = (const float*)d_in[0];
    const float* W   = (const float*)d_in[1];
    if (in_sizes[0] == IN_CH * OUT_CH * OUT_U * 8) {       // defensive order check
        W = (const float*)d_in[0];
        inp = (const float*)d_in[1];
    }
    float* out = (float*)d_out;

    cudaFuncSetAttribute(k_mma, cudaFuncAttributeMaxDynamicSharedMemorySize, SM_TOTAL);

    dim3 gg(KSPLIT, 2), gt(NIK / 32, BATCH / 32), gr1(40, 8);

    k_splitW<<<MO / 256, 256>>>(W);                        // Bc(c=0.1) + blog=0
    k_split_x<<<gt, 256>>>(inp);
    // epoch 1
    k_mma<<<gg, 256, SM_TOTAL>>>(0);
    k_red1<<<gr1, 256>>>();
    k_red2<<<40, 256>>>(nullptr, 1);                       // v0 -> vT
    k_mma<<<gg, 256, SM_TOTAL>>>(1);
    k_bdot<<<IN_CH, 160>>>(W);                             // b1 -> c1 -> Bc
    // epoch 2
    k_mma<<<gg, 256, SM_TOTAL>>>(0);
    k_red1<<<gr1, 256>>>();
    k_red2<<<40, 256>>>(nullptr, 1);                       // v1 -> vT
    k_mma<<<gg, 256, SM_TOTAL>>>(1);
    k_bdot<<<IN_CH, 160>>>(W);                             // b2 -> c2 -> Bc
    // epoch 3
    k_mma<<<gg, 256, SM_TOTAL>>>(0);
    k_red1<<<gr1, 256>>>();
    k_red2<<<40, 256>>>(out, 0);                           // v2 -> output
}